// round 13
// baseline (speedup 1.0000x reference)
#include <cuda_runtime.h>
#include <cuda_fp16.h>
#include <cstdint>

#define NNODES 8192
#define CDIM   64
#define KNN    9

typedef unsigned long long u64t;
typedef unsigned int u32t;

__device__ float4 g_sq4[NNODES / 4];
__device__ float  g_z[NNODES * CDIM];
__device__ float  g_y[NNODES * CDIM];
__device__ uint4  g_h16[NNODES * 8];
__device__ uint4  g_m16[NNODES * 8];

__device__ __forceinline__ int batch_of(int i) { return (i * 8) / 8191; }
__device__ __forceinline__ float f_ninf() { return __int_as_float(0xff800000); }

__device__ __forceinline__ void fma2(u64t& d, u64t a, u64t b) {
    asm("fma.rn.f32x2 %0, %1, %2, %0;" : "+l"(d) : "l"(a), "l"(b));
}
__device__ __forceinline__ float pairsum(u64t v) {
    float lo, hi;
    asm("mov.b64 {%0, %1}, %2;" : "=f"(lo), "=f"(hi) : "l"(v));
    return lo + hi;
}
__device__ __forceinline__ void cpa16(u32t sa, const void* g) {
    asm volatile("cp.async.cg.shared.global [%0], [%1], 16;" :: "r"(sa), "l"(g));
}
#define CPA_COMMIT() asm volatile("cp.async.commit_group;")
#define CPA_WAIT0()  asm volatile("cp.async.wait_group 0;" ::: "memory")

__device__ __forceinline__ u32t smem_u32(const void* p) {
    u32t a;
    asm("{ .reg .u64 tmp; cvta.to.shared.u64 tmp, %1; cvt.u32.u64 %0, tmp; }"
        : "=r"(a) : "l"(p));
    return a;
}
__device__ __forceinline__ void ldsm4(u32t* r, u32t addr) {
    asm volatile("ldmatrix.sync.aligned.m8n8.x4.shared.b16 {%0,%1,%2,%3}, [%4];"
        : "=r"(r[0]), "=r"(r[1]), "=r"(r[2]), "=r"(r[3]) : "r"(addr));
}
__device__ __forceinline__ void mma16816(float* c, const u32t* a, const u32t* b) {
    asm volatile("mma.sync.aligned.m16n8k16.row.col.f32.f16.f16.f32 "
        "{%0,%1,%2,%3}, {%4,%5,%6,%7}, {%8,%9}, {%0,%1,%2,%3};"
        : "+f"(c[0]), "+f"(c[1]), "+f"(c[2]), "+f"(c[3])
        : "r"(a[0]), "r"(a[1]), "r"(a[2]), "r"(a[3]), "r"(b[0]), "r"(b[1]));
}

// ---------------------------------------------------------------------------
// Fused kernel 1: transpose + fp16 h/m images + sq + both linear GEMMs.
// (unchanged from round 9/11 — verified)
// ---------------------------------------------------------------------------
#define OFF_S   0
#define OFF_XS  16640
#define OFF_WL  33024
#define OFF_WR  50432
#define PG_SMEM 67840

__global__ void __launch_bounds__(256, 1)
k_pg(const float* __restrict__ x, const float* __restrict__ Wl,
     const float* __restrict__ bl, const float* __restrict__ Wr) {
    extern __shared__ char sm[];
    u32t sb = smem_u32(sm);
    float (*s)[65] = (float(*)[65])(sm + OFF_S);
    float* xs      = (float*)(sm + OFF_XS);
    float (*wl)[68] = (float(*)[68])(sm + OFF_WL);
    float (*wr)[68] = (float(*)[68])(sm + OFF_WR);

    int t = threadIdx.x;
    int tile = blockIdx.x;
    int b = tile >> 4;
    int hw0 = (tile & 15) << 6;
    int w = t & 63, g = t >> 6;

    #pragma unroll
    for (int r = 0; r < 4; r++) {
        int idx = r * 256 + t;
        int o = idx >> 4, c4 = idx & 15;
        cpa16(sb + OFF_WL + o * 272 + c4 * 16, ((const float4*)Wl) + idx);
        cpa16(sb + OFF_WR + o * 272 + c4 * 16, ((const float4*)Wr) + idx);
    }
    CPA_COMMIT();

    #pragma unroll
    for (int r = 0; r < 16; r++) {
        int c = r * 4 + g;
        s[c][w] = x[(((b << 6) + c) << 10) | (hw0 + w)];
    }
    int l = t & 31;
    float bll = bl[l], blh = bl[l + 32];
    __syncthreads();

    int base = (b << 10) + hw0;
    {
        int nl = t >> 2;
        int c0 = (t & 3) << 4;
        #pragma unroll
        for (int gg = 0; gg < 2; gg++) {
            u32t hw4[4], mw4[4];
            #pragma unroll
            for (int pp = 0; pp < 4; pp++) {
                float v0 = s[c0 + gg * 8 + pp * 2][nl];
                float v1 = s[c0 + gg * 8 + pp * 2 + 1][nl];
                __half h0 = __float2half_rn(v0), h1 = __float2half_rn(v1);
                float r0 = v0 - __half2float(h0), r1 = v1 - __half2float(h1);
                __half m0 = __float2half_rn(r0), m1 = __float2half_rn(r1);
                __half2 hh = __halves2half2(h0, h1);
                __half2 mm = __halves2half2(m0, m1);
                hw4[pp] = *(u32t*)&hh;
                mw4[pp] = *(u32t*)&mm;
            }
            int idx = (base + nl) * 8 + (t & 3) * 2 + gg;
            g_h16[idx] = make_uint4(hw4[0], hw4[1], hw4[2], hw4[3]);
            g_m16[idx] = make_uint4(mw4[0], mw4[1], mw4[2], mw4[3]);
        }
    }
    if (t < 64) {
        float acc = 0.f;
        #pragma unroll
        for (int c = 0; c < 64; c++) { float v = s[c][t]; acc = fmaf(v, v, acc); }
        ((float*)g_sq4)[base + t] = acc;
    }
    {
        int nl = t >> 2;
        int c0 = (t & 3) << 4;
        #pragma unroll
        for (int pp = 0; pp < 4; pp++) {
            float4 v = make_float4(s[c0 + pp * 4][nl], s[c0 + pp * 4 + 1][nl],
                                   s[c0 + pp * 4 + 2][nl], s[c0 + pp * 4 + 3][nl]);
            *(float4*)&xs[nl * 64 + c0 + pp * 4] = v;
        }
    }
    CPA_WAIT0();
    __syncthreads();

    int ng = t >> 5;
    u64t az0[8], az1[8], ay0[8], ay1[8];
    #pragma unroll
    for (int i = 0; i < 8; i++) { az0[i] = az1[i] = ay0[i] = ay1[i] = 0ull; }

    #pragma unroll
    for (int c4 = 0; c4 < 16; c4++) {
        ulonglong2 w0 = *(ulonglong2*)&wl[l][c4 * 4];
        ulonglong2 w1 = *(ulonglong2*)&wl[l + 32][c4 * 4];
        ulonglong2 w2 = *(ulonglong2*)&wr[l][c4 * 4];
        ulonglong2 w3 = *(ulonglong2*)&wr[l + 32][c4 * 4];
        #pragma unroll
        for (int nn = 0; nn < 8; nn++) {
            ulonglong2 xv = *(ulonglong2*)(xs + (ng * 8 + nn) * 64 + c4 * 4);
            fma2(az0[nn], xv.x, w0.x); fma2(az0[nn], xv.y, w0.y);
            fma2(az1[nn], xv.x, w1.x); fma2(az1[nn], xv.y, w1.y);
            fma2(ay0[nn], xv.x, w2.x); fma2(ay0[nn], xv.y, w2.y);
            fma2(ay1[nn], xv.x, w3.x); fma2(ay1[nn], xv.y, w3.y);
        }
    }
    #pragma unroll
    for (int nn = 0; nn < 8; nn++) {
        int gg = (base + ng * 8 + nn) * 64;
        g_z[gg + l]      = pairsum(az0[nn]);
        g_z[gg + l + 32] = pairsum(az1[nn]);
        g_y[gg + l]      = pairsum(ay0[nn]) + bll;
        g_y[gg + l + 32] = pairsum(ay1[nn]) + blh;
    }
}

// ---------------------------------------------------------------------------
// Kernel 2: HMMA distances with FRAGMENT-LOCAL top-9 (no dist smem).
// i-tile 32, grid 256, 256 threads, 2 CTAs/SM. 1 barrier/iteration.
// warps: (warp&1) -> m16 block, (warp>>1) -> n16 window; j-tile 128 (2 imgs).
// Thread keeps two top-9 lists (rows r0, r0+8); 16-way merge per row at end.
// ---------------------------------------------------------------------------
#define OFF_A    0           // h 4608 + m 4608 (32 rows x 144B each)
#define OFF_B    9216        // 2 bufs x (2 img x (h 9216 + m 9216)) = 73728
#define OFF_SQJ  82944       // 4096
#define OFF_SEL  87040       // 32*9*4 = 1152
#define OFF_CNT  88192       // 128
#define K_SMEM   88320
#define OFF_CD   9216        // overlay on B after loop: 32*16*9*4 = 18432
#define OFF_CI   27648       // + 18432 = 46080

__device__ __forceinline__ float4 f4add(float4 a, float4 b) {
    return make_float4(a.x + b.x, a.y + b.y, a.z + b.z, a.w + b.w);
}
__device__ __forceinline__ float4 f4madd(float4 a, float s, float4 b) {
    return make_float4(fmaf(a.x, s, b.x), fmaf(a.y, s, b.y),
                       fmaf(a.z, s, b.z), fmaf(a.w, s, b.w));
}

// 128-node j-window (2 images x h+m) = 2048 uint4; 8 per thread (256 thr)
__device__ __forceinline__ void prefetch_j128(u32t dstbase, int jt, int t) {
    #pragma unroll
    for (int k = 0; k < 8; k++) {
        int idx = k * 256 + t;
        int img = idx >> 10, rem = idx & 1023;
        int sp = rem >> 9, r3 = rem & 511;
        int row = r3 >> 3, c = r3 & 7;
        const uint4* src = (sp ? g_m16 : g_h16) + ((jt + img) * 64 + row) * 8 + c;
        cpa16(dstbase + img * 18432 + sp * 9216 + row * 144 + c * 16, src);
    }
}

__global__ void __launch_bounds__(256, 2)
k_knn(float* __restrict__ out) {
    extern __shared__ char sm[];
    u32t sb = smem_u32(sm);
    float* sqj  = (float*)(sm + OFF_SQJ);
    float* cd   = (float*)(sm + OFF_CD);
    int*   ci   = (int*)(sm + OFF_CI);
    int*   sel  = (int*)(sm + OFF_SEL);
    int*   scnt = (int*)(sm + OFF_CNT);

    int t = threadIdx.x;
    int warp = t >> 5, lane = t & 31;
    int i0 = blockIdx.x * 32;
    int b = batch_of(i0);
    int jt0 = b << 4;
    bool spc = (b == 7);

    int mb = warp & 1, nw = warp >> 1;
    int m0 = mb * 16;
    int nwin = nw * 16;

    // initial loads: A image (32 rows h+m = 512 uint4), sqj (256), B window 0
    #pragma unroll
    for (int k = 0; k < 2; k++) {
        int idx = k * 256 + t;
        int sp = idx >> 8, rem = idx & 255;
        int row = rem >> 3, c = rem & 7;
        const uint4* src = (sp ? g_m16 : g_h16) + (blockIdx.x * 32 + row) * 8 + c;
        cpa16(sb + OFF_A + sp * 4608 + row * 144 + c * 16, src);
    }
    cpa16(sb + OFF_SQJ + t * 16, g_sq4 + (b << 8) + t);
    prefetch_j128(sb + OFF_B, jt0, t);
    CPA_COMMIT();
    CPA_WAIT0();
    __syncthreads();

    // persistent A fragments
    u32t Ah[4][4], Am[4][4];
    {
        u32t abase = sb + OFF_A + (m0 + (lane & 15)) * 144 + (lane >> 4) * 16;
        #pragma unroll
        for (int k = 0; k < 4; k++) {
            ldsm4(Ah[k], abase + k * 32);
            ldsm4(Am[k], abase + 4608 + k * 32);
        }
    }

    // two register top-9 lists (rows r0 = i0+m0+(lane>>2), r1 = r0+8)
    float wb0[KNN], wb1[KNN]; int ib0[KNN], ib1[KNN];
    #pragma unroll
    for (int k = 0; k < KNN; k++) {
        wb0[k] = f_ninf(); ib0[k] = 0x7fffffff;
        wb1[k] = f_ninf(); ib1[k] = 0x7fffffff;
    }

    bool killj = (nw == 3) && ((lane & 3) == 3);           // owns col 8191's cand
    bool row1_is8 = (i0 + m0 + (lane >> 2) + 8) == 8191;

    u32t boff = ((lane >> 4) * 8 + (lane & 7)) * 144 + ((lane >> 3) & 1) * 16;
    int sqbase = nwin + (lane & 3) * 2;
    int jbth = (b << 10) + sqbase;

    #pragma unroll 1
    for (int it = 0; it < 8; it++) {
        if (it < 7)
            prefetch_j128(sb + OFF_B + ((it + 1) & 1) * 36864, jt0 + 2 * (it + 1), t);
        CPA_COMMIT();

        u32t bufb = sb + OFF_B + (it & 1) * 36864;
        float C[2][2][4];
        #pragma unroll
        for (int img = 0; img < 2; img++)
            #pragma unroll
            for (int nb = 0; nb < 2; nb++)
                #pragma unroll
                for (int e = 0; e < 4; e++) C[img][nb][e] = 0.f;

        #pragma unroll
        for (int img = 0; img < 2; img++) {
            u32t hb = bufb + img * 18432 + nwin * 144 + boff;
            u32t mba = hb + 9216;
            #pragma unroll
            for (int k = 0; k < 4; k++) {
                u32t bh[4], bm[4];
                ldsm4(bh, hb + k * 32);
                ldsm4(bm, mba + k * 32);
                mma16816(C[img][0], Ah[k], &bh[0]);
                mma16816(C[img][1], Ah[k], &bh[2]);
                mma16816(C[img][0], Am[k], &bh[0]);
                mma16816(C[img][1], Am[k], &bh[2]);
                mma16816(C[img][0], Ah[k], &bm[0]);
                mma16816(C[img][1], Ah[k], &bm[2]);
            }
        }

        // fragment-local select. cand k = img*4 + nb*2 + e ; j ascending in k.
        float wv0[8], wv1[8];
        #pragma unroll
        for (int img = 0; img < 2; img++)
            #pragma unroll
            for (int nb = 0; nb < 2; nb++) {
                float2 sj = *(const float2*)(sqj + it * 128 + img * 64 + sqbase + nb * 8);
                int k = img * 4 + nb * 2;
                wv0[k]     = fmaf(2.f, C[img][nb][0], -sj.x);
                wv0[k + 1] = fmaf(2.f, C[img][nb][1], -sj.y);
                wv1[k]     = fmaf(2.f, C[img][nb][2], -sj.x);
                wv1[k + 1] = fmaf(2.f, C[img][nb][3], -sj.y);
            }

        if (spc) {
            bool j8 = (it == 7) && killj;           // cand 7 is node 8191
            if (j8) wv0[7] = f_ninf();
            if (row1_is8) {
                float keep = j8 ? wv1[7] : f_ninf();
                #pragma unroll
                for (int k = 0; k < 8; k++) wv1[k] = f_ninf();
                wv1[7] = keep;
            } else if (j8) {
                wv1[7] = f_ninf();
            }
        }

        int jb = jbth + it * 128;
        const int joff[8] = {0, 1, 8, 9, 64, 65, 72, 73};
        {
            float m = wv0[0];
            #pragma unroll
            for (int k = 1; k < 8; k++) m = fmaxf(m, wv0[k]);
            if (m > wb0[KNN - 1]) {
                #pragma unroll
                for (int k = 0; k < 8; k++) {
                    float d = wv0[k];
                    if (d > wb0[KNN - 1]) {
                        float nwv = d; int ni = jb + joff[k];
                        #pragma unroll
                        for (int s = 0; s < KNN; s++) {
                            if (nwv > wb0[s]) {
                                float t1 = wb0[s]; int t2 = ib0[s];
                                wb0[s] = nwv; ib0[s] = ni;
                                nwv = t1; ni = t2;
                            }
                        }
                    }
                }
            }
        }
        {
            float m = wv1[0];
            #pragma unroll
            for (int k = 1; k < 8; k++) m = fmaxf(m, wv1[k]);
            if (m > wb1[KNN - 1]) {
                #pragma unroll
                for (int k = 0; k < 8; k++) {
                    float d = wv1[k];
                    if (d > wb1[KNN - 1]) {
                        float nwv = d; int ni = jb + joff[k];
                        #pragma unroll
                        for (int s = 0; s < KNN; s++) {
                            if (nwv > wb1[s]) {
                                float t1 = wb1[s]; int t2 = ib1[s];
                                wb1[s] = nwv; ib1[s] = ni;
                                nwv = t1; ni = t2;
                            }
                        }
                    }
                }
            }
        }

        CPA_WAIT0();
        __syncthreads();        // B[it+1] ready; buf ((it+1)&1) reads all done
    }

    // dump lists (overlay on dead B region)
    {
        int r0l = m0 + (lane >> 2);
        int l = nw * 4 + (lane & 3);
        #pragma unroll
        for (int k = 0; k < KNN; k++) {
            cd[(r0l * 16 + l) * KNN + k] = wb0[k];
            ci[(r0l * 16 + l) * KNN + k] = ib0[k];
            cd[((r0l + 8) * 16 + l) * KNN + k] = wb1[k];
            ci[((r0l + 8) * 16 + l) * KNN + k] = ib1[k];
        }
    }
    __syncthreads();

    // 16-way merge per row: largest w first, tie -> lower index
    if (t < 32) {
        int ptr[16];
        #pragma unroll
        for (int l = 0; l < 16; l++) ptr[l] = 0;
        int cnt = 0;
        #pragma unroll
        for (int k = 0; k < KNN; k++) {
            float bw = f_ninf(); int bidx = 0x7fffffff; int bl2 = 0;
            #pragma unroll
            for (int l = 0; l < 16; l++) {
                int o = (t * 16 + l) * KNN + ptr[l];
                float wd = cd[o]; int ii = ci[o];
                if (wd > bw || (wd == bw && ii < bidx)) { bw = wd; bidx = ii; bl2 = l; }
            }
            ptr[bl2]++;
            sel[t * KNN + k] = bidx;
            if (bw > f_ninf()) cnt++;
        }
        if (cnt == 0) { sel[t * KNN] = i0 + t; cnt = 1; }
        scnt[t] = cnt;
    }
    __syncthreads();

    // epilogue: 8 threads/node x 8 channels
    int ie = t >> 3, part = t & 7;
    int gi = i0 + ie;
    float4 a0 = {0,0,0,0}, a1 = {0,0,0,0};
    int cnt = scnt[ie];
    for (int k = 0; k < cnt; k++) {
        const float4* zr = (const float4*)(g_z + sel[ie * KNN + k] * 64 + part * 8);
        a0 = f4add(a0, zr[0]);
        a1 = f4add(a1, zr[1]);
    }
    float inv = 1.0f / (float)cnt;
    const float4* yr = (const float4*)(g_y + gi * 64 + part * 8);
    float4* op = (float4*)(out + gi * 64 + part * 8);
    op[0] = f4madd(a0, inv, yr[0]);
    op[1] = f4madd(a1, inv, yr[1]);
}

// ---------------------------------------------------------------------------
extern "C" void kernel_launch(void* const* d_in, const int* in_sizes, int n_in,
                              void* d_out, int out_size) {
    (void)in_sizes; (void)n_in; (void)out_size;
    const float* x  = (const float*)d_in[0];
    const float* Wl = (const float*)d_in[1];
    const float* bl = (const float*)d_in[2];
    const float* Wr = (const float*)d_in[3];
    float* out = (float*)d_out;

    cudaFuncSetAttribute(k_pg,  cudaFuncAttributeMaxDynamicSharedMemorySize, PG_SMEM);
    cudaFuncSetAttribute(k_knn, cudaFuncAttributeMaxDynamicSharedMemorySize, K_SMEM);

    k_pg<<<128, 256, PG_SMEM>>>(x, Wl, bl, Wr);
    k_knn<<<256, 256, K_SMEM>>>(out);
}

// round 14
// speedup vs baseline: 1.2540x; 1.2540x over previous
#include <cuda_runtime.h>
#include <cuda_fp16.h>
#include <cstdint>

#define NNODES 8192
#define CDIM   64
#define KNN    9

typedef unsigned long long u64t;
typedef unsigned int u32t;

__device__ float4 g_sq4[NNODES / 4];
__device__ float  g_z[NNODES * CDIM];
__device__ float  g_y[NNODES * CDIM];
__device__ uint4  g_h16[NNODES * 8];
__device__ uint4  g_m16[NNODES * 8];

__device__ __forceinline__ int batch_of(int i) { return (i * 8) / 8191; }
__device__ __forceinline__ float f_ninf() { return __int_as_float(0xff800000); }

__device__ __forceinline__ void fma2(u64t& d, u64t a, u64t b) {
    asm("fma.rn.f32x2 %0, %1, %2, %0;" : "+l"(d) : "l"(a), "l"(b));
}
__device__ __forceinline__ float pairsum(u64t v) {
    float lo, hi;
    asm("mov.b64 {%0, %1}, %2;" : "=f"(lo), "=f"(hi) : "l"(v));
    return lo + hi;
}
__device__ __forceinline__ void cpa16(u32t sa, const void* g) {
    asm volatile("cp.async.cg.shared.global [%0], [%1], 16;" :: "r"(sa), "l"(g));
}
#define CPA_COMMIT() asm volatile("cp.async.commit_group;")
#define CPA_WAIT0()  asm volatile("cp.async.wait_group 0;" ::: "memory")

__device__ __forceinline__ u32t smem_u32(const void* p) {
    u32t a;
    asm("{ .reg .u64 tmp; cvta.to.shared.u64 tmp, %1; cvt.u32.u64 %0, tmp; }"
        : "=r"(a) : "l"(p));
    return a;
}
__device__ __forceinline__ void ldsm4(u32t* r, u32t addr) {
    asm volatile("ldmatrix.sync.aligned.m8n8.x4.shared.b16 {%0,%1,%2,%3}, [%4];"
        : "=r"(r[0]), "=r"(r[1]), "=r"(r[2]), "=r"(r[3]) : "r"(addr));
}
__device__ __forceinline__ void mma16816(float* c, const u32t* a, const u32t* b) {
    asm volatile("mma.sync.aligned.m16n8k16.row.col.f32.f16.f16.f32 "
        "{%0,%1,%2,%3}, {%4,%5,%6,%7}, {%8,%9}, {%0,%1,%2,%3};"
        : "+f"(c[0]), "+f"(c[1]), "+f"(c[2]), "+f"(c[3])
        : "r"(a[0]), "r"(a[1]), "r"(a[2]), "r"(a[3]), "r"(b[0]), "r"(b[1]));
}

// ---------------------------------------------------------------------------
// Fused kernel 1: transpose + fp16 h/m images + sq + both linear GEMMs.
// (verified since round 9)
// ---------------------------------------------------------------------------
#define OFF_S   0
#define OFF_XS  16640
#define OFF_WL  33024
#define OFF_WR  50432
#define PG_SMEM 67840

__global__ void __launch_bounds__(256, 1)
k_pg(const float* __restrict__ x, const float* __restrict__ Wl,
     const float* __restrict__ bl, const float* __restrict__ Wr) {
    extern __shared__ char sm[];
    u32t sb = smem_u32(sm);
    float (*s)[65] = (float(*)[65])(sm + OFF_S);
    float* xs      = (float*)(sm + OFF_XS);
    float (*wl)[68] = (float(*)[68])(sm + OFF_WL);
    float (*wr)[68] = (float(*)[68])(sm + OFF_WR);

    int t = threadIdx.x;
    int tile = blockIdx.x;
    int b = tile >> 4;
    int hw0 = (tile & 15) << 6;
    int w = t & 63, g = t >> 6;

    #pragma unroll
    for (int r = 0; r < 4; r++) {
        int idx = r * 256 + t;
        int o = idx >> 4, c4 = idx & 15;
        cpa16(sb + OFF_WL + o * 272 + c4 * 16, ((const float4*)Wl) + idx);
        cpa16(sb + OFF_WR + o * 272 + c4 * 16, ((const float4*)Wr) + idx);
    }
    CPA_COMMIT();

    #pragma unroll
    for (int r = 0; r < 16; r++) {
        int c = r * 4 + g;
        s[c][w] = x[(((b << 6) + c) << 10) | (hw0 + w)];
    }
    int l = t & 31;
    float bll = bl[l], blh = bl[l + 32];
    __syncthreads();

    int base = (b << 10) + hw0;
    {
        int nl = t >> 2;
        int c0 = (t & 3) << 4;
        #pragma unroll
        for (int gg = 0; gg < 2; gg++) {
            u32t hw4[4], mw4[4];
            #pragma unroll
            for (int pp = 0; pp < 4; pp++) {
                float v0 = s[c0 + gg * 8 + pp * 2][nl];
                float v1 = s[c0 + gg * 8 + pp * 2 + 1][nl];
                __half h0 = __float2half_rn(v0), h1 = __float2half_rn(v1);
                float r0 = v0 - __half2float(h0), r1 = v1 - __half2float(h1);
                __half m0 = __float2half_rn(r0), m1 = __float2half_rn(r1);
                __half2 hh = __halves2half2(h0, h1);
                __half2 mm = __halves2half2(m0, m1);
                hw4[pp] = *(u32t*)&hh;
                mw4[pp] = *(u32t*)&mm;
            }
            int idx = (base + nl) * 8 + (t & 3) * 2 + gg;
            g_h16[idx] = make_uint4(hw4[0], hw4[1], hw4[2], hw4[3]);
            g_m16[idx] = make_uint4(mw4[0], mw4[1], mw4[2], mw4[3]);
        }
    }
    if (t < 64) {
        float acc = 0.f;
        #pragma unroll
        for (int c = 0; c < 64; c++) { float v = s[c][t]; acc = fmaf(v, v, acc); }
        ((float*)g_sq4)[base + t] = acc;
    }
    {
        int nl = t >> 2;
        int c0 = (t & 3) << 4;
        #pragma unroll
        for (int pp = 0; pp < 4; pp++) {
            float4 v = make_float4(s[c0 + pp * 4][nl], s[c0 + pp * 4 + 1][nl],
                                   s[c0 + pp * 4 + 2][nl], s[c0 + pp * 4 + 3][nl]);
            *(float4*)&xs[nl * 64 + c0 + pp * 4] = v;
        }
    }
    CPA_WAIT0();
    __syncthreads();

    int ng = t >> 5;
    u64t az0[8], az1[8], ay0[8], ay1[8];
    #pragma unroll
    for (int i = 0; i < 8; i++) { az0[i] = az1[i] = ay0[i] = ay1[i] = 0ull; }

    #pragma unroll
    for (int c4 = 0; c4 < 16; c4++) {
        ulonglong2 w0 = *(ulonglong2*)&wl[l][c4 * 4];
        ulonglong2 w1 = *(ulonglong2*)&wl[l + 32][c4 * 4];
        ulonglong2 w2 = *(ulonglong2*)&wr[l][c4 * 4];
        ulonglong2 w3 = *(ulonglong2*)&wr[l + 32][c4 * 4];
        #pragma unroll
        for (int nn = 0; nn < 8; nn++) {
            ulonglong2 xv = *(ulonglong2*)(xs + (ng * 8 + nn) * 64 + c4 * 4);
            fma2(az0[nn], xv.x, w0.x); fma2(az0[nn], xv.y, w0.y);
            fma2(az1[nn], xv.x, w1.x); fma2(az1[nn], xv.y, w1.y);
            fma2(ay0[nn], xv.x, w2.x); fma2(ay0[nn], xv.y, w2.y);
            fma2(ay1[nn], xv.x, w3.x); fma2(ay1[nn], xv.y, w3.y);
        }
    }
    #pragma unroll
    for (int nn = 0; nn < 8; nn++) {
        int gg = (base + ng * 8 + nn) * 64;
        g_z[gg + l]      = pairsum(az0[nn]);
        g_z[gg + l + 32] = pairsum(az1[nn]);
        g_y[gg + l]      = pairsum(ay0[nn]) + bll;
        g_y[gg + l + 32] = pairsum(ay1[nn]) + blh;
    }
}

// ---------------------------------------------------------------------------
// Kernel 2 (R11 base + software-pipelined select): HMMA distances, j-tile 128,
// 8 iterations, 1 barrier/iter. Select of iter t-1 runs inside iter t, placed
// between the MMA issue block and the dist STS so it fills HMMA latency.
// Hazards: select(t) reads dist[(t-1)&1] (written at t-1, synced at barrier
// t-1; next overwrite is the STS at t+1, which is after barrier t). 
// ---------------------------------------------------------------------------
#define OFF_A    0           // h 9216 + m 9216
#define OFF_B    18432       // 2 bufs x 36864 (2 images x (h+m))
#define OFF_DIST 92160       // 2 bufs x 34816
#define OFF_SQJ  161792      // 4096
#define OFF_SEL  165888      // 2304
#define OFF_CNT  168192      // 256
#define K_SMEM   168448
#define OFF_CD   0           // overlay: 512*9*4 = 18432 (A dead after frags)
#define OFF_CI   18432       // overlay on B buf0

__device__ __forceinline__ float4 f4add(float4 a, float4 b) {
    return make_float4(a.x + b.x, a.y + b.y, a.z + b.z, a.w + b.w);
}
__device__ __forceinline__ float4 f4madd(float4 a, float s, float4 b) {
    return make_float4(fmaf(a.x, s, b.x), fmaf(a.y, s, b.y),
                       fmaf(a.z, s, b.z), fmaf(a.w, s, b.w));
}

// copy a 128-node j-window (2 images x (h+m)) into a buf; 2048 uint4, 4/thread
__device__ __forceinline__ void prefetch_j128(u32t dstbase, int jt, int t) {
    #pragma unroll
    for (int k = 0; k < 4; k++) {
        int idx = k * 512 + t;
        int img = idx >> 10, rem = idx & 1023;
        int sp = rem >> 9, r3 = rem & 511;
        int row = r3 >> 3, c = r3 & 7;
        const uint4* src = (sp ? g_m16 : g_h16) + ((jt + img) * 64 + row) * 8 + c;
        cpa16(dstbase + img * 18432 + sp * 9216 + row * 144 + c * 16, src);
    }
}

__global__ void __launch_bounds__(512, 1)
k_knn(float* __restrict__ out) {
    extern __shared__ char sm[];
    u32t sb = smem_u32(sm);
    float* dist = (float*)(sm + OFF_DIST);
    float* sqj  = (float*)(sm + OFF_SQJ);
    float* cd   = (float*)(sm + OFF_CD);
    int*   ci   = (int*)(sm + OFF_CI);
    int*   sel  = (int*)(sm + OFF_SEL);
    int*   scnt = (int*)(sm + OFF_CNT);

    int t = threadIdx.x;
    int warp = t >> 5, lane = t & 31;
    int i0 = blockIdx.x * 64;
    int b = batch_of(i0);
    int jt0 = b << 4;
    bool spc = (b == 7);

    int iown = t & 63, q = t >> 6;          // 8 stripes of 16 logical cols
    bool ib8 = (i0 + iown) == 8191;

    // initial loads: A image, sqj, B window 0
    #pragma unroll
    for (int k = 0; k < 2; k++) {
        int idx = k * 512 + t;
        int sp = idx >> 9, rem = idx & 511;
        int row = rem >> 3, c = rem & 7;
        const uint4* src = (sp ? g_m16 : g_h16) + (blockIdx.x * 64 + row) * 8 + c;
        cpa16(sb + OFF_A + sp * 9216 + row * 144 + c * 16, src);
    }
    if (t < 256) cpa16(sb + OFF_SQJ + t * 16, g_sq4 + (b << 8) + t);
    prefetch_j128(sb + OFF_B, jt0, t);
    CPA_COMMIT();
    CPA_WAIT0();
    __syncthreads();

    int m0 = (warp & 3) * 16;
    int nwin = (warp >> 2) * 16;
    u32t Ah[4][4], Am[4][4];
    {
        u32t abase = sb + (m0 + (lane & 15)) * 144 + (lane >> 4) * 16;
        #pragma unroll
        for (int k = 0; k < 4; k++) {
            ldsm4(Ah[k], abase + OFF_A + k * 32);
            ldsm4(Am[k], abase + OFF_A + 9216 + k * 32);
        }
    }

    float wbest[KNN]; int ibest[KNN];
    #pragma unroll
    for (int k = 0; k < KNN; k++) { wbest[k] = f_ninf(); ibest[k] = 0x7fffffff; }

    u32t boff = ((lane >> 4) * 8 + (lane & 7)) * 144 + ((lane >> 3) & 1) * 16;

    // deferred select of iteration `sit` (reads dist[sit&1])
    auto do_select = [&](int sit) {
        const float* drow = dist + (sit & 1) * 8704 + (q >> 2) * 4352
                          + iown * 68 + (q & 3) * 16;
        const float* srow = sqj + sit * 128 + q * 16;
        float4 d0 = *(const float4*)(drow + 0);
        float4 d1 = *(const float4*)(drow + 4);
        float4 d2 = *(const float4*)(drow + 8);
        float4 d3 = *(const float4*)(drow + 12);
        float4 s0 = *(const float4*)(srow + 0);
        float4 s1 = *(const float4*)(srow + 4);
        float4 s2 = *(const float4*)(srow + 8);
        float4 s3 = *(const float4*)(srow + 12);
        float4 w0 = make_float4(fmaf(2.f, d0.x, -s0.x), fmaf(2.f, d0.y, -s0.y),
                                fmaf(2.f, d0.z, -s0.z), fmaf(2.f, d0.w, -s0.w));
        float4 w1 = make_float4(fmaf(2.f, d1.x, -s1.x), fmaf(2.f, d1.y, -s1.y),
                                fmaf(2.f, d1.z, -s1.z), fmaf(2.f, d1.w, -s1.w));
        float4 w2 = make_float4(fmaf(2.f, d2.x, -s2.x), fmaf(2.f, d2.y, -s2.y),
                                fmaf(2.f, d2.z, -s2.z), fmaf(2.f, d2.w, -s2.w));
        float4 w3 = make_float4(fmaf(2.f, d3.x, -s3.x), fmaf(2.f, d3.y, -s3.y),
                                fmaf(2.f, d3.z, -s3.z), fmaf(2.f, d3.w, -s3.w));
        if (spc) {
            bool last = (sit == 7) && (q == 7);
            if (ib8) {
                float keep = last ? w3.w : f_ninf();
                float ni = f_ninf();
                w0 = make_float4(ni, ni, ni, ni);
                w1 = w0; w2 = w0;
                w3 = make_float4(ni, ni, ni, keep);
            } else if (last) {
                w3.w = f_ninf();
            }
        }
        float m01 = fmaxf(fmaxf(w0.x, w0.y), fmaxf(w0.z, w0.w));
        float m23 = fmaxf(fmaxf(w1.x, w1.y), fmaxf(w1.z, w1.w));
        float m45 = fmaxf(fmaxf(w2.x, w2.y), fmaxf(w2.z, w2.w));
        float m67 = fmaxf(fmaxf(w3.x, w3.y), fmaxf(w3.z, w3.w));
        float mall = fmaxf(fmaxf(m01, m23), fmaxf(m45, m67));
        if (mall > wbest[KNN - 1]) {
            int j0 = (b << 10) + sit * 128 + q * 16;
            float wv[16] = {w0.x, w0.y, w0.z, w0.w, w1.x, w1.y, w1.z, w1.w,
                            w2.x, w2.y, w2.z, w2.w, w3.x, w3.y, w3.z, w3.w};
            #pragma unroll
            for (int k = 0; k < 16; k++) {
                float d = wv[k];
                if (d > wbest[KNN - 1]) {
                    float nw = d; int ni = j0 + k;
                    #pragma unroll
                    for (int s = 0; s < KNN; s++) {
                        if (nw > wbest[s]) {
                            float t1 = wbest[s]; int t2 = ibest[s];
                            wbest[s] = nw; ibest[s] = ni;
                            nw = t1; ni = t2;
                        }
                    }
                }
            }
        }
    };

    #pragma unroll 1
    for (int it = 0; it < 8; it++) {
        if (it < 7)
            prefetch_j128(sb + OFF_B + ((it + 1) & 1) * 36864, jt0 + 2 * (it + 1), t);
        CPA_COMMIT();

        u32t bufb = sb + OFF_B + (it & 1) * 36864;
        float C[2][2][4];
        #pragma unroll
        for (int img = 0; img < 2; img++)
            #pragma unroll
            for (int nb = 0; nb < 2; nb++)
                #pragma unroll
                for (int e = 0; e < 4; e++) C[img][nb][e] = 0.f;

        #pragma unroll
        for (int img = 0; img < 2; img++) {
            u32t hb = bufb + img * 18432 + nwin * 144 + boff;
            u32t mb = hb + 9216;
            #pragma unroll
            for (int k = 0; k < 4; k++) {
                u32t bh[4], bm[4];
                ldsm4(bh, hb + k * 32);
                ldsm4(bm, mb + k * 32);
                mma16816(C[img][0], Ah[k], &bh[0]);
                mma16816(C[img][1], Ah[k], &bh[2]);
                mma16816(C[img][0], Am[k], &bh[0]);
                mma16816(C[img][1], Am[k], &bh[2]);
                mma16816(C[img][0], Ah[k], &bm[0]);
                mma16816(C[img][1], Ah[k], &bm[2]);
            }
        }

        // deferred select of the PREVIOUS iteration, issued while HMMA results
        // are still in flight (independent of C / current B buffer).
        if (it > 0) do_select(it - 1);

        // write dots to dist[it&1] (consumes C -> naturally after HMMA drain)
        {
            float* dbuf = dist + (it & 1) * 8704;
            int r0 = m0 + (lane >> 2);
            int cb = nwin + (lane & 3) * 2;
            #pragma unroll
            for (int img = 0; img < 2; img++) {
                float* dp = dbuf + img * 4352;
                #pragma unroll
                for (int nb = 0; nb < 2; nb++) {
                    *(float2*)(dp + r0 * 68 + cb + nb * 8) =
                        make_float2(C[img][nb][0], C[img][nb][1]);
                    *(float2*)(dp + (r0 + 8) * 68 + cb + nb * 8) =
                        make_float2(C[img][nb][2], C[img][nb][3]);
                }
            }
        }
        CPA_WAIT0();
        __syncthreads();        // the only barrier per iteration
    }
    do_select(7);               // drain the pipeline
    __syncthreads();            // selects done before cd/ci overlay writes

    #pragma unroll
    for (int k = 0; k < KNN; k++) {
        cd[(iown * 8 + q) * KNN + k] = wbest[k];
        ci[(iown * 8 + q) * KNN + k] = ibest[k];
    }
    __syncthreads();

    // 8-way merge per node: largest w first, tie -> lower index (top_k stable)
    if (t < 64) {
        int ptr[8] = {0, 0, 0, 0, 0, 0, 0, 0};
        int cnt = 0;
        #pragma unroll
        for (int k = 0; k < KNN; k++) {
            float bw = f_ninf(); int bidx = 0x7fffffff; int bl2 = 0;
            #pragma unroll
            for (int l2 = 0; l2 < 8; l2++) {
                int o = (t * 8 + l2) * KNN + ptr[l2];
                float wd = cd[o]; int ii = ci[o];
                if (wd > bw || (wd == bw && ii < bidx)) { bw = wd; bidx = ii; bl2 = l2; }
            }
            ptr[bl2]++;
            sel[t * KNN + k] = bidx;
            if (bw > f_ninf()) cnt++;
        }
        if (cnt == 0) { sel[t * KNN] = i0 + t; cnt = 1; }
        scnt[t] = cnt;
    }
    __syncthreads();

    // epilogue: 8 threads/node x 8 channels
    int ie = t >> 3, part = t & 7;
    int gi = i0 + ie;
    float4 a0 = {0,0,0,0}, a1 = {0,0,0,0};
    int cnt = scnt[ie];
    for (int k = 0; k < cnt; k++) {
        const float4* zr = (const float4*)(g_z + sel[ie * KNN + k] * 64 + part * 8);
        a0 = f4add(a0, zr[0]);
        a1 = f4add(a1, zr[1]);
    }
    float inv = 1.0f / (float)cnt;
    const float4* yr = (const float4*)(g_y + gi * 64 + part * 8);
    float4* op = (float4*)(out + gi * 64 + part * 8);
    op[0] = f4madd(a0, inv, yr[0]);
    op[1] = f4madd(a1, inv, yr[1]);
}

// ---------------------------------------------------------------------------
extern "C" void kernel_launch(void* const* d_in, const int* in_sizes, int n_in,
                              void* d_out, int out_size) {
    (void)in_sizes; (void)n_in; (void)out_size;
    const float* x  = (const float*)d_in[0];
    const float* Wl = (const float*)d_in[1];
    const float* bl = (const float*)d_in[2];
    const float* Wr = (const float*)d_in[3];
    float* out = (float*)d_out;

    cudaFuncSetAttribute(k_pg,  cudaFuncAttributeMaxDynamicSharedMemorySize, PG_SMEM);
    cudaFuncSetAttribute(k_knn, cudaFuncAttributeMaxDynamicSharedMemorySize, K_SMEM);

    k_pg<<<128, 256, PG_SMEM>>>(x, Wl, bl, Wr);
    k_knn<<<128, 512, K_SMEM>>>(out);
}

// round 15
// speedup vs baseline: 1.4954x; 1.1926x over previous
#include <cuda_runtime.h>
#include <cuda_fp16.h>
#include <cstdint>

#define NNODES 8192
#define CDIM   64
#define KNN    9

typedef unsigned long long u64t;
typedef unsigned int u32t;

__device__ float4 g_sq4[NNODES / 4];
__device__ float  g_z[NNODES * CDIM];
__device__ float  g_y[NNODES * CDIM];
__device__ uint4  g_h16[NNODES * 8];
__device__ uint4  g_m16[NNODES * 8];

__device__ __forceinline__ int batch_of(int i) { return (i * 8) / 8191; }
__device__ __forceinline__ float f_ninf() { return __int_as_float(0xff800000); }

__device__ __forceinline__ void fma2(u64t& d, u64t a, u64t b) {
    asm("fma.rn.f32x2 %0, %1, %2, %0;" : "+l"(d) : "l"(a), "l"(b));
}
__device__ __forceinline__ float pairsum(u64t v) {
    float lo, hi;
    asm("mov.b64 {%0, %1}, %2;" : "=f"(lo), "=f"(hi) : "l"(v));
    return lo + hi;
}
__device__ __forceinline__ void cpa16(u32t sa, const void* g) {
    asm volatile("cp.async.cg.shared.global [%0], [%1], 16;" :: "r"(sa), "l"(g));
}
#define CPA_COMMIT() asm volatile("cp.async.commit_group;")
#define CPA_WAIT0()  asm volatile("cp.async.wait_group 0;" ::: "memory")

__device__ __forceinline__ u32t smem_u32(const void* p) {
    u32t a;
    asm("{ .reg .u64 tmp; cvta.to.shared.u64 tmp, %1; cvt.u32.u64 %0, tmp; }"
        : "=r"(a) : "l"(p));
    return a;
}
__device__ __forceinline__ void ldsm4(u32t* r, u32t addr) {
    asm volatile("ldmatrix.sync.aligned.m8n8.x4.shared.b16 {%0,%1,%2,%3}, [%4];"
        : "=r"(r[0]), "=r"(r[1]), "=r"(r[2]), "=r"(r[3]) : "r"(addr));
}
__device__ __forceinline__ void mma16816(float* c, const u32t* a, const u32t* b) {
    asm volatile("mma.sync.aligned.m16n8k16.row.col.f32.f16.f16.f32 "
        "{%0,%1,%2,%3}, {%4,%5,%6,%7}, {%8,%9}, {%0,%1,%2,%3};"
        : "+f"(c[0]), "+f"(c[1]), "+f"(c[2]), "+f"(c[3])
        : "r"(a[0]), "r"(a[1]), "r"(a[2]), "r"(a[3]), "r"(b[0]), "r"(b[1]));
}

// ---------------------------------------------------------------------------
// Fused kernel 1: transpose + fp16 h/m images + sq + both linear GEMMs.
// (verified since round 9)
// ---------------------------------------------------------------------------
#define OFF_S   0
#define OFF_XS  16640
#define OFF_WL  33024
#define OFF_WR  50432
#define PG_SMEM 67840

__global__ void __launch_bounds__(256, 1)
k_pg(const float* __restrict__ x, const float* __restrict__ Wl,
     const float* __restrict__ bl, const float* __restrict__ Wr) {
    extern __shared__ char sm[];
    u32t sb = smem_u32(sm);
    float (*s)[65] = (float(*)[65])(sm + OFF_S);
    float* xs      = (float*)(sm + OFF_XS);
    float (*wl)[68] = (float(*)[68])(sm + OFF_WL);
    float (*wr)[68] = (float(*)[68])(sm + OFF_WR);

    int t = threadIdx.x;
    int tile = blockIdx.x;
    int b = tile >> 4;
    int hw0 = (tile & 15) << 6;
    int w = t & 63, g = t >> 6;

    #pragma unroll
    for (int r = 0; r < 4; r++) {
        int idx = r * 256 + t;
        int o = idx >> 4, c4 = idx & 15;
        cpa16(sb + OFF_WL + o * 272 + c4 * 16, ((const float4*)Wl) + idx);
        cpa16(sb + OFF_WR + o * 272 + c4 * 16, ((const float4*)Wr) + idx);
    }
    CPA_COMMIT();

    #pragma unroll
    for (int r = 0; r < 16; r++) {
        int c = r * 4 + g;
        s[c][w] = x[(((b << 6) + c) << 10) | (hw0 + w)];
    }
    int l = t & 31;
    float bll = bl[l], blh = bl[l + 32];
    __syncthreads();

    int base = (b << 10) + hw0;
    {
        int nl = t >> 2;
        int c0 = (t & 3) << 4;
        #pragma unroll
        for (int gg = 0; gg < 2; gg++) {
            u32t hw4[4], mw4[4];
            #pragma unroll
            for (int pp = 0; pp < 4; pp++) {
                float v0 = s[c0 + gg * 8 + pp * 2][nl];
                float v1 = s[c0 + gg * 8 + pp * 2 + 1][nl];
                __half h0 = __float2half_rn(v0), h1 = __float2half_rn(v1);
                float r0 = v0 - __half2float(h0), r1 = v1 - __half2float(h1);
                __half m0 = __float2half_rn(r0), m1 = __float2half_rn(r1);
                __half2 hh = __halves2half2(h0, h1);
                __half2 mm = __halves2half2(m0, m1);
                hw4[pp] = *(u32t*)&hh;
                mw4[pp] = *(u32t*)&mm;
            }
            int idx = (base + nl) * 8 + (t & 3) * 2 + gg;
            g_h16[idx] = make_uint4(hw4[0], hw4[1], hw4[2], hw4[3]);
            g_m16[idx] = make_uint4(mw4[0], mw4[1], mw4[2], mw4[3]);
        }
    }
    if (t < 64) {
        float acc = 0.f;
        #pragma unroll
        for (int c = 0; c < 64; c++) { float v = s[c][t]; acc = fmaf(v, v, acc); }
        ((float*)g_sq4)[base + t] = acc;
    }
    {
        int nl = t >> 2;
        int c0 = (t & 3) << 4;
        #pragma unroll
        for (int pp = 0; pp < 4; pp++) {
            float4 v = make_float4(s[c0 + pp * 4][nl], s[c0 + pp * 4 + 1][nl],
                                   s[c0 + pp * 4 + 2][nl], s[c0 + pp * 4 + 3][nl]);
            *(float4*)&xs[nl * 64 + c0 + pp * 4] = v;
        }
    }
    CPA_WAIT0();
    __syncthreads();

    int ng = t >> 5;
    u64t az0[8], az1[8], ay0[8], ay1[8];
    #pragma unroll
    for (int i = 0; i < 8; i++) { az0[i] = az1[i] = ay0[i] = ay1[i] = 0ull; }

    #pragma unroll
    for (int c4 = 0; c4 < 16; c4++) {
        ulonglong2 w0 = *(ulonglong2*)&wl[l][c4 * 4];
        ulonglong2 w1 = *(ulonglong2*)&wl[l + 32][c4 * 4];
        ulonglong2 w2 = *(ulonglong2*)&wr[l][c4 * 4];
        ulonglong2 w3 = *(ulonglong2*)&wr[l + 32][c4 * 4];
        #pragma unroll
        for (int nn = 0; nn < 8; nn++) {
            ulonglong2 xv = *(ulonglong2*)(xs + (ng * 8 + nn) * 64 + c4 * 4);
            fma2(az0[nn], xv.x, w0.x); fma2(az0[nn], xv.y, w0.y);
            fma2(az1[nn], xv.x, w1.x); fma2(az1[nn], xv.y, w1.y);
            fma2(ay0[nn], xv.x, w2.x); fma2(ay0[nn], xv.y, w2.y);
            fma2(ay1[nn], xv.x, w3.x); fma2(ay1[nn], xv.y, w3.y);
        }
    }
    #pragma unroll
    for (int nn = 0; nn < 8; nn++) {
        int gg = (base + ng * 8 + nn) * 64;
        g_z[gg + l]      = pairsum(az0[nn]);
        g_z[gg + l + 32] = pairsum(az1[nn]);
        g_y[gg + l]      = pairsum(ay0[nn]) + bll;
        g_y[gg + l + 32] = pairsum(ay1[nn]) + blh;
    }
}

// ---------------------------------------------------------------------------
// Kernel 2 (R14 base, insert chain made BRANCHLESS via SEL ternaries).
// HMMA distances, j-tile 128, 8 iterations, 1 barrier/iter, pipelined select.
// ---------------------------------------------------------------------------
#define OFF_A    0           // h 9216 + m 9216
#define OFF_B    18432       // 2 bufs x 36864 (2 images x (h+m))
#define OFF_DIST 92160       // 2 bufs x 34816
#define OFF_SQJ  161792      // 4096
#define OFF_SEL  165888      // 2304
#define OFF_CNT  168192      // 256
#define K_SMEM   168448
#define OFF_CD   0           // overlay: 512*9*4 = 18432 (A dead after frags)
#define OFF_CI   18432       // overlay on B buf0

__device__ __forceinline__ float4 f4add(float4 a, float4 b) {
    return make_float4(a.x + b.x, a.y + b.y, a.z + b.z, a.w + b.w);
}
__device__ __forceinline__ float4 f4madd(float4 a, float s, float4 b) {
    return make_float4(fmaf(a.x, s, b.x), fmaf(a.y, s, b.y),
                       fmaf(a.z, s, b.z), fmaf(a.w, s, b.w));
}

// copy a 128-node j-window (2 images x (h+m)) into a buf; 2048 uint4, 4/thread
__device__ __forceinline__ void prefetch_j128(u32t dstbase, int jt, int t) {
    #pragma unroll
    for (int k = 0; k < 4; k++) {
        int idx = k * 512 + t;
        int img = idx >> 10, rem = idx & 1023;
        int sp = rem >> 9, r3 = rem & 511;
        int row = r3 >> 3, c = r3 & 7;
        const uint4* src = (sp ? g_m16 : g_h16) + ((jt + img) * 64 + row) * 8 + c;
        cpa16(dstbase + img * 18432 + sp * 9216 + row * 144 + c * 16, src);
    }
}

__global__ void __launch_bounds__(512, 1)
k_knn(float* __restrict__ out) {
    extern __shared__ char sm[];
    u32t sb = smem_u32(sm);
    float* dist = (float*)(sm + OFF_DIST);
    float* sqj  = (float*)(sm + OFF_SQJ);
    float* cd   = (float*)(sm + OFF_CD);
    int*   ci   = (int*)(sm + OFF_CI);
    int*   sel  = (int*)(sm + OFF_SEL);
    int*   scnt = (int*)(sm + OFF_CNT);

    int t = threadIdx.x;
    int warp = t >> 5, lane = t & 31;
    int i0 = blockIdx.x * 64;
    int b = batch_of(i0);
    int jt0 = b << 4;
    bool spc = (b == 7);

    int iown = t & 63, q = t >> 6;          // 8 stripes of 16 logical cols
    bool ib8 = (i0 + iown) == 8191;

    // initial loads: A image, sqj, B window 0
    #pragma unroll
    for (int k = 0; k < 2; k++) {
        int idx = k * 512 + t;
        int sp = idx >> 9, rem = idx & 511;
        int row = rem >> 3, c = rem & 7;
        const uint4* src = (sp ? g_m16 : g_h16) + (blockIdx.x * 64 + row) * 8 + c;
        cpa16(sb + OFF_A + sp * 9216 + row * 144 + c * 16, src);
    }
    if (t < 256) cpa16(sb + OFF_SQJ + t * 16, g_sq4 + (b << 8) + t);
    prefetch_j128(sb + OFF_B, jt0, t);
    CPA_COMMIT();
    CPA_WAIT0();
    __syncthreads();

    int m0 = (warp & 3) * 16;
    int nwin = (warp >> 2) * 16;
    u32t Ah[4][4], Am[4][4];
    {
        u32t abase = sb + (m0 + (lane & 15)) * 144 + (lane >> 4) * 16;
        #pragma unroll
        for (int k = 0; k < 4; k++) {
            ldsm4(Ah[k], abase + OFF_A + k * 32);
            ldsm4(Am[k], abase + OFF_A + 9216 + k * 32);
        }
    }

    float wbest[KNN]; int ibest[KNN];
    #pragma unroll
    for (int k = 0; k < KNN; k++) { wbest[k] = f_ninf(); ibest[k] = 0x7fffffff; }

    u32t boff = ((lane >> 4) * 8 + (lane & 7)) * 144 + ((lane >> 3) & 1) * 16;

    // deferred select of iteration `sit` (reads dist[sit&1]).
    // Insert chain is BRANCHLESS: 9 predicated compare/select steps, no BSSY.
    auto do_select = [&](int sit) {
        const float* drow = dist + (sit & 1) * 8704 + (q >> 2) * 4352
                          + iown * 68 + (q & 3) * 16;
        const float* srow = sqj + sit * 128 + q * 16;
        float4 d0 = *(const float4*)(drow + 0);
        float4 d1 = *(const float4*)(drow + 4);
        float4 d2 = *(const float4*)(drow + 8);
        float4 d3 = *(const float4*)(drow + 12);
        float4 s0 = *(const float4*)(srow + 0);
        float4 s1 = *(const float4*)(srow + 4);
        float4 s2 = *(const float4*)(srow + 8);
        float4 s3 = *(const float4*)(srow + 12);
        float4 w0 = make_float4(fmaf(2.f, d0.x, -s0.x), fmaf(2.f, d0.y, -s0.y),
                                fmaf(2.f, d0.z, -s0.z), fmaf(2.f, d0.w, -s0.w));
        float4 w1 = make_float4(fmaf(2.f, d1.x, -s1.x), fmaf(2.f, d1.y, -s1.y),
                                fmaf(2.f, d1.z, -s1.z), fmaf(2.f, d1.w, -s1.w));
        float4 w2 = make_float4(fmaf(2.f, d2.x, -s2.x), fmaf(2.f, d2.y, -s2.y),
                                fmaf(2.f, d2.z, -s2.z), fmaf(2.f, d2.w, -s2.w));
        float4 w3 = make_float4(fmaf(2.f, d3.x, -s3.x), fmaf(2.f, d3.y, -s3.y),
                                fmaf(2.f, d3.z, -s3.z), fmaf(2.f, d3.w, -s3.w));
        if (spc) {
            bool last = (sit == 7) && (q == 7);
            if (ib8) {
                float keep = last ? w3.w : f_ninf();
                float ni = f_ninf();
                w0 = make_float4(ni, ni, ni, ni);
                w1 = w0; w2 = w0;
                w3 = make_float4(ni, ni, ni, keep);
            } else if (last) {
                w3.w = f_ninf();
            }
        }
        float m01 = fmaxf(fmaxf(w0.x, w0.y), fmaxf(w0.z, w0.w));
        float m23 = fmaxf(fmaxf(w1.x, w1.y), fmaxf(w1.z, w1.w));
        float m45 = fmaxf(fmaxf(w2.x, w2.y), fmaxf(w2.z, w2.w));
        float m67 = fmaxf(fmaxf(w3.x, w3.y), fmaxf(w3.z, w3.w));
        float mall = fmaxf(fmaxf(m01, m23), fmaxf(m45, m67));
        if (mall > wbest[KNN - 1]) {
            int j0 = (b << 10) + sit * 128 + q * 16;
            float wv[16] = {w0.x, w0.y, w0.z, w0.w, w1.x, w1.y, w1.z, w1.w,
                            w2.x, w2.y, w2.z, w2.w, w3.x, w3.y, w3.z, w3.w};
            #pragma unroll
            for (int k = 0; k < 16; k++) {
                float d = wv[k];
                if (d > wbest[KNN - 1]) {
                    float nw = d; int ni = j0 + k;
                    #pragma unroll
                    for (int s = 0; s < KNN; s++) {
                        bool gt = nw > wbest[s];
                        float tv = wbest[s]; int ti = ibest[s];
                        wbest[s] = gt ? nw : wbest[s];
                        ibest[s] = gt ? ni : ibest[s];
                        nw = gt ? tv : nw;
                        ni = gt ? ti : ni;
                    }
                }
            }
        }
    };

    #pragma unroll 1
    for (int it = 0; it < 8; it++) {
        if (it < 7)
            prefetch_j128(sb + OFF_B + ((it + 1) & 1) * 36864, jt0 + 2 * (it + 1), t);
        CPA_COMMIT();

        u32t bufb = sb + OFF_B + (it & 1) * 36864;
        float C[2][2][4];
        #pragma unroll
        for (int img = 0; img < 2; img++)
            #pragma unroll
            for (int nb = 0; nb < 2; nb++)
                #pragma unroll
                for (int e = 0; e < 4; e++) C[img][nb][e] = 0.f;

        #pragma unroll
        for (int img = 0; img < 2; img++) {
            u32t hb = bufb + img * 18432 + nwin * 144 + boff;
            u32t mb = hb + 9216;
            #pragma unroll
            for (int k = 0; k < 4; k++) {
                u32t bh[4], bm[4];
                ldsm4(bh, hb + k * 32);
                ldsm4(bm, mb + k * 32);
                mma16816(C[img][0], Ah[k], &bh[0]);
                mma16816(C[img][1], Ah[k], &bh[2]);
                mma16816(C[img][0], Am[k], &bh[0]);
                mma16816(C[img][1], Am[k], &bh[2]);
                mma16816(C[img][0], Ah[k], &bm[0]);
                mma16816(C[img][1], Ah[k], &bm[2]);
            }
        }

        // deferred select of the PREVIOUS iteration (fills HMMA latency)
        if (it > 0) do_select(it - 1);

        // write dots to dist[it&1]
        {
            float* dbuf = dist + (it & 1) * 8704;
            int r0 = m0 + (lane >> 2);
            int cb = nwin + (lane & 3) * 2;
            #pragma unroll
            for (int img = 0; img < 2; img++) {
                float* dp = dbuf + img * 4352;
                #pragma unroll
                for (int nb = 0; nb < 2; nb++) {
                    *(float2*)(dp + r0 * 68 + cb + nb * 8) =
                        make_float2(C[img][nb][0], C[img][nb][1]);
                    *(float2*)(dp + (r0 + 8) * 68 + cb + nb * 8) =
                        make_float2(C[img][nb][2], C[img][nb][3]);
                }
            }
        }
        CPA_WAIT0();
        __syncthreads();        // the only barrier per iteration
    }
    do_select(7);               // drain
    __syncthreads();            // selects done before cd/ci overlay writes

    #pragma unroll
    for (int k = 0; k < KNN; k++) {
        cd[(iown * 8 + q) * KNN + k] = wbest[k];
        ci[(iown * 8 + q) * KNN + k] = ibest[k];
    }
    __syncthreads();

    // 8-way merge per node: largest w first, tie -> lower index (top_k stable)
    if (t < 64) {
        int ptr[8] = {0, 0, 0, 0, 0, 0, 0, 0};
        int cnt = 0;
        #pragma unroll
        for (int k = 0; k < KNN; k++) {
            float bw = f_ninf(); int bidx = 0x7fffffff; int bl2 = 0;
            #pragma unroll
            for (int l2 = 0; l2 < 8; l2++) {
                int o = (t * 8 + l2) * KNN + ptr[l2];
                float wd = cd[o]; int ii = ci[o];
                bool tk = (wd > bw) || (wd == bw && ii < bidx);
                bw = tk ? wd : bw;
                bidx = tk ? ii : bidx;
                bl2 = tk ? l2 : bl2;
            }
            ptr[bl2]++;
            sel[t * KNN + k] = bidx;
            if (bw > f_ninf()) cnt++;
        }
        if (cnt == 0) { sel[t * KNN] = i0 + t; cnt = 1; }
        scnt[t] = cnt;
    }
    __syncthreads();

    // epilogue: 8 threads/node x 8 channels
    int ie = t >> 3, part = t & 7;
    int gi = i0 + ie;
    float4 a0 = {0,0,0,0}, a1 = {0,0,0,0};
    int cnt = scnt[ie];
    for (int k = 0; k < cnt; k++) {
        const float4* zr = (const float4*)(g_z + sel[ie * KNN + k] * 64 + part * 8);
        a0 = f4add(a0, zr[0]);
        a1 = f4add(a1, zr[1]);
    }
    float inv = 1.0f / (float)cnt;
    const float4* yr = (const float4*)(g_y + gi * 64 + part * 8);
    float4* op = (float4*)(out + gi * 64 + part * 8);
    op[0] = f4madd(a0, inv, yr[0]);
    op[1] = f4madd(a1, inv, yr[1]);
}

// ---------------------------------------------------------------------------
extern "C" void kernel_launch(void* const* d_in, const int* in_sizes, int n_in,
                              void* d_out, int out_size) {
    (void)in_sizes; (void)n_in; (void)out_size;
    const float* x  = (const float*)d_in[0];
    const float* Wl = (const float*)d_in[1];
    const float* bl = (const float*)d_in[2];
    const float* Wr = (const float*)d_in[3];
    float* out = (float*)d_out;

    cudaFuncSetAttribute(k_pg,  cudaFuncAttributeMaxDynamicSharedMemorySize, PG_SMEM);
    cudaFuncSetAttribute(k_knn, cudaFuncAttributeMaxDynamicSharedMemorySize, K_SMEM);

    k_pg<<<128, 256, PG_SMEM>>>(x, Wl, bl, Wr);
    k_knn<<<128, 512, K_SMEM>>>(out);
}